// round 3
// baseline (speedup 1.0000x reference)
#include <cuda_runtime.h>
#include <cuda_bf16.h>
#include <math.h>

// Problem constants
#define BB    16
#define LL    128
#define DD    512
#define HH    256
#define TAGS  45
#define LP1   129   // L + 1 (root prepended)

#define TM    8     // rows per block in kernel 1
#define GI    8     // i-rows per block in kernel 2

// Scratch (device globals — no allocation allowed)
__device__ float g_ha[BB * LL * HH];     // hidden @ Wa           (2 MB)
__device__ float g_hb[BB * LL * HH];     // hidden @ Wb           (2 MB)
__device__ float g_hbroot[HH];           // root @ Wb
__device__ float g_ce[BB * LL];          // per-token (arc_ce + lab_ce) * mask

// ---------------------------------------------------------------------------
// Kernel 1: hidden = relu(X @ W1 + b1); ha = hidden @ Wa; hb = hidden @ Wb
// Blocks 0..255 each handle TM=8 flat rows of (b,l). Block 256 computes
// g_hbroot = root @ Wb.
// ---------------------------------------------------------------------------
__global__ __launch_bounds__(256) void k1_proj(
    const float* __restrict__ x,     // [B,L,D]
    const float* __restrict__ W1,    // [D,H]
    const float* __restrict__ b1,    // [H]
    const float* __restrict__ root,  // [H]
    const float* __restrict__ Wp)    // [2H,H]
{
    const int h = threadIdx.x;

    if (blockIdx.x == (BB * LL) / TM) {
        // root block: hbroot[h] = sum_k root[k] * Wp[(H+k)*H + h]
        float acc = 0.f;
        #pragma unroll 4
        for (int k = 0; k < HH; k++)
            acc = fmaf(root[k], Wp[(HH + k) * HH + h], acc);
        g_hbroot[h] = acc;
        return;
    }

    __shared__ float xs[TM][DD];   // 16 KB
    __shared__ float hs[TM][HH];   // 8 KB

    const int row0 = blockIdx.x * TM;

    // Load X tile (coalesced float4)
    {
        const float4* xg = reinterpret_cast<const float4*>(x + (size_t)row0 * DD);
        float4* xsv = reinterpret_cast<float4*>(&xs[0][0]);
        #pragma unroll
        for (int i = threadIdx.x; i < TM * DD / 4; i += 256)
            xsv[i] = xg[i];
    }
    __syncthreads();

    // Stage 1: hidden[r][h] = relu(sum_d xs[r][d]*W1[d][h] + b1[h])
    {
        float acc[TM];
        const float bias = b1[h];
        #pragma unroll
        for (int r = 0; r < TM; r++) acc[r] = bias;

        for (int d = 0; d < DD; d += 4) {
            const float w0 = W1[(d + 0) * HH + h];
            const float w1 = W1[(d + 1) * HH + h];
            const float w2 = W1[(d + 2) * HH + h];
            const float w3 = W1[(d + 3) * HH + h];
            #pragma unroll
            for (int r = 0; r < TM; r++) {
                float4 xv = *reinterpret_cast<const float4*>(&xs[r][d]);
                acc[r] = fmaf(xv.x, w0, acc[r]);
                acc[r] = fmaf(xv.y, w1, acc[r]);
                acc[r] = fmaf(xv.z, w2, acc[r]);
                acc[r] = fmaf(xv.w, w3, acc[r]);
            }
        }
        #pragma unroll
        for (int r = 0; r < TM; r++) hs[r][h] = fmaxf(acc[r], 0.f);
    }
    __syncthreads();

    // Stage 2: ha[r][h] = sum_k hs[r][k]*Wp[k][h]; hb[r][h] = sum_k hs[r][k]*Wp[H+k][h]
    {
        float acca[TM], accb[TM];
        #pragma unroll
        for (int r = 0; r < TM; r++) { acca[r] = 0.f; accb[r] = 0.f; }

        for (int k = 0; k < HH; k += 4) {
            const float wa0 = Wp[(k + 0) * HH + h];
            const float wa1 = Wp[(k + 1) * HH + h];
            const float wa2 = Wp[(k + 2) * HH + h];
            const float wa3 = Wp[(k + 3) * HH + h];
            const float wb0 = Wp[(HH + k + 0) * HH + h];
            const float wb1 = Wp[(HH + k + 1) * HH + h];
            const float wb2 = Wp[(HH + k + 2) * HH + h];
            const float wb3 = Wp[(HH + k + 3) * HH + h];
            #pragma unroll
            for (int r = 0; r < TM; r++) {
                float4 hv = *reinterpret_cast<const float4*>(&hs[r][k]);
                acca[r] = fmaf(hv.x, wa0, acca[r]);
                acca[r] = fmaf(hv.y, wa1, acca[r]);
                acca[r] = fmaf(hv.z, wa2, acca[r]);
                acca[r] = fmaf(hv.w, wa3, acca[r]);
                accb[r] = fmaf(hv.x, wb0, accb[r]);
                accb[r] = fmaf(hv.y, wb1, accb[r]);
                accb[r] = fmaf(hv.z, wb2, accb[r]);
                accb[r] = fmaf(hv.w, wb3, accb[r]);
            }
        }
        #pragma unroll
        for (int r = 0; r < TM; r++) {
            g_ha[(size_t)(row0 + r) * HH + h] = acca[r];
            g_hb[(size_t)(row0 + r) * HH + h] = accb[r];
        }
    }
}

// ---------------------------------------------------------------------------
// Kernel 2: for each (b, i): arc logits over j=0..128 (computed on the fly),
// arc log-softmax CE; gathered sel = relu(ha_i + hb_{j*} + bp); label logits,
// label log-softmax CE. Writes g_ce[b*L+i] = mask * (arc_ce + lab_ce).
// One block per (b, group of GI=8 i-rows). 256 threads = 8 warps.
// ---------------------------------------------------------------------------
__global__ __launch_bounds__(256) void k2_score(
    const int*   __restrict__ slen,     // [B]
    const int*   __restrict__ darcs,    // [B,L]
    const int*   __restrict__ dlabs,    // [B,L]
    const float* __restrict__ bp,       // [H]
    const float* __restrict__ W_arc,    // [H,1]
    const float* __restrict__ W_lab,    // [H,TAGS]
    const float* __restrict__ b_lab)    // [TAGS]
{
    __shared__ float sha[GI][HH];        // ha rows + bp   (8 KB)
    __shared__ float warc[HH];           // 1 KB
    __shared__ float slog[GI][132];      // arc logits     (~4.2 KB)
    __shared__ float ssel[GI][HH];       // gathered pair repr (8 KB)
    __shared__ float slab[GI][48];       // label logits   (1.5 KB)

    const int t    = threadIdx.x;
    const int w    = t >> 5;
    const int lane = t & 31;

    const int b  = blockIdx.x / (LL / GI);
    const int ig = blockIdx.x % (LL / GI);
    const int i0 = ig * GI;
    const int len = slen[b];

    // Load ha rows (+bp) and W_arc
    warc[t] = W_arc[t];
    #pragma unroll
    for (int r = 0; r < GI; r++)
        sha[r][t] = g_ha[(size_t)(b * LL + i0 + r) * HH + t] + bp[t];
    __syncthreads();

    // ---- Arc logits: warp w handles j = w, w+8, ... ----
    for (int j = w; j < LP1; j += 8) {
        const float* hbj = (j == 0) ? g_hbroot
                                    : &g_hb[(size_t)(b * LL + (j - 1)) * HH];
        float p[GI];
        #pragma unroll
        for (int r = 0; r < GI; r++) p[r] = 0.f;

        #pragma unroll
        for (int t8 = 0; t8 < 8; t8++) {
            const int k = lane + 32 * t8;
            const float hv = hbj[k];
            const float wv = warc[k];
            #pragma unroll
            for (int r = 0; r < GI; r++)
                p[r] = fmaf(fmaxf(sha[r][k] + hv, 0.f), wv, p[r]);
        }
        #pragma unroll
        for (int r = 0; r < GI; r++) {
            float v = p[r];
            #pragma unroll
            for (int off = 16; off; off >>= 1)
                v += __shfl_xor_sync(0xffffffffu, v, off);
            p[r] = v;
        }
        if (lane == 0) {
            #pragma unroll
            for (int r = 0; r < GI; r++) slog[r][j] = p[r];
        }
    }
    __syncthreads();

    // ---- Arc log-softmax: warp w handles row r = w ----
    float arc_ce = 0.f;
    {
        const int r = w;
        float m = -INFINITY;
        for (int jj = lane; jj < LP1; jj += 32) m = fmaxf(m, slog[r][jj]);
        #pragma unroll
        for (int off = 16; off; off >>= 1)
            m = fmaxf(m, __shfl_xor_sync(0xffffffffu, m, off));
        float s = 0.f;
        for (int jj = lane; jj < LP1; jj += 32) s += expf(slog[r][jj] - m);
        #pragma unroll
        for (int off = 16; off; off >>= 1)
            s += __shfl_xor_sync(0xffffffffu, s, off);
        const float lse = m + logf(s);
        const int ja = darcs[b * LL + i0 + r];
        arc_ce = lse - slog[r][ja];
    }

    // ---- Gathered sel = relu(ha + hb[j*] + bp), all threads ----
    #pragma unroll
    for (int r = 0; r < GI; r++) {
        const int ja = darcs[b * LL + i0 + r];
        const float* hbj = (ja == 0) ? g_hbroot
                                     : &g_hb[(size_t)(b * LL + (ja - 1)) * HH];
        ssel[r][t] = fmaxf(sha[r][t] + hbj[t], 0.f);
    }
    __syncthreads();

    // ---- Label logits: 360 dots of length 256 spread over threads ----
    for (int q = t; q < GI * TAGS; q += 256) {
        const int r = q / TAGS;
        const int tag = q % TAGS;
        float a = b_lab[tag];
        #pragma unroll 4
        for (int k = 0; k < HH; k++)
            a = fmaf(ssel[r][k], W_lab[k * TAGS + tag], a);
        slab[r][tag] = a;
    }
    __syncthreads();

    // ---- Label log-softmax: warp w handles row r = w ----
    {
        const int r = w;
        float m = -INFINITY;
        for (int tg = lane; tg < TAGS; tg += 32) m = fmaxf(m, slab[r][tg]);
        #pragma unroll
        for (int off = 16; off; off >>= 1)
            m = fmaxf(m, __shfl_xor_sync(0xffffffffu, m, off));
        float s = 0.f;
        for (int tg = lane; tg < TAGS; tg += 32) s += expf(slab[r][tg] - m);
        #pragma unroll
        for (int off = 16; off; off >>= 1)
            s += __shfl_xor_sync(0xffffffffu, s, off);
        const float lse = m + logf(s);
        const int tl = dlabs[b * LL + i0 + r];
        const float lab_ce = lse - slab[r][tl];

        if (lane == 0) {
            const int i = i0 + r;
            g_ce[b * LL + i] = (i < len) ? (arc_ce + lab_ce) : 0.f;
        }
    }
}

// ---------------------------------------------------------------------------
// Kernel 3: final reduction -> scalar loss
// ---------------------------------------------------------------------------
__global__ __launch_bounds__(256) void k3_reduce(
    const int* __restrict__ slen, float* __restrict__ out)
{
    __shared__ float red[256];
    float s = 0.f;
    for (int i = threadIdx.x; i < BB * LL; i += 256) s += g_ce[i];
    red[threadIdx.x] = s;
    __syncthreads();
    #pragma unroll
    for (int st = 128; st > 0; st >>= 1) {
        if (threadIdx.x < st) red[threadIdx.x] += red[threadIdx.x + st];
        __syncthreads();
    }
    if (threadIdx.x == 0) {
        float denom = 0.f;
        #pragma unroll
        for (int bb = 0; bb < BB; bb++) denom += (float)slen[bb];
        denom = fmaxf(denom, 1.f);
        out[0] = red[0] / denom * 0.5f;
    }
}

// ---------------------------------------------------------------------------
// Input order (metadata.txt):
// 0 contextualized [B,L,D] f32     1 sentence_lengths [B] i32
// 2 desired_arcs [B,L] i32         3 desired_labels [B,L] i32
// 4 W1 [D,H] f32                   5 b1 [H] f32
// 6 root [H] f32                   7 Wp [2H,H] f32
// 8 bp [H] f32                     9 W_arc [H,1] f32
// 10 b_arc [1] f32                 11 W_lab [H,TAGS] f32
// 12 b_lab [TAGS] f32
// ---------------------------------------------------------------------------
extern "C" void kernel_launch(void* const* d_in, const int* in_sizes, int n_in,
                              void* d_out, int out_size)
{
    const float* x     = (const float*)d_in[0];
    const int*   slen  = (const int*)  d_in[1];
    const int*   darcs = (const int*)  d_in[2];
    const int*   dlabs = (const int*)  d_in[3];
    const float* W1    = (const float*)d_in[4];
    const float* b1    = (const float*)d_in[5];
    const float* root  = (const float*)d_in[6];
    const float* Wp    = (const float*)d_in[7];
    const float* bp    = (const float*)d_in[8];
    const float* W_arc = (const float*)d_in[9];
    const float* W_lab = (const float*)d_in[11];
    const float* b_lab = (const float*)d_in[12];
    float* out = (float*)d_out;

    k1_proj <<< (BB * LL) / TM + 1, 256 >>>(x, W1, b1, root, Wp);
    k2_score<<< BB * (LL / GI),     256 >>>(slen, darcs, dlabs, bp, W_arc, W_lab, b_lab);
    k3_reduce<<< 1,                 256 >>>(slen, out);
}